// round 3
// baseline (speedup 1.0000x reference)
#include <cuda_runtime.h>
#include <math.h>

// Problem constants (fixed by the reference setup_inputs)
#define BB 8
#define NN 16384
#define G 64
#define NC (G * G * G)
#define NGRIDS 16                  // (batch, side): side 0 = pred, 1 = target
#define XMIN (-5.0f)
#define CS 0.15625f                // 10/64, exact in binary
#define INV_CS 6.4f
#define CS_SAFE 0.15624f           // strictly-conservative cell size for the termination bound

// Static device scratch (allocation-free, graph-capture safe)
__device__ int    g_count[NGRIDS * NC];          // per-cell counts, reused as scatter cursor
__device__ int    g_start[NGRIDS * (NC + 1)];    // exclusive prefix (cell ranges)
__device__ float4 g_pts[NGRIDS * NN];            // cell-sorted points
__device__ double g_acc[2];                      // [0] noise L1 sum, [1] chamfer min-d2 sum

__device__ __forceinline__ int cell_of(float v) {
    int c = (int)floorf((v - XMIN) * INV_CS);
    return min(max(c, 0), G - 1);
}

// ---------------------------------------------------------------------------
__global__ void zero_kernel() {
    const int n = NGRIDS * NC;
    for (int i = blockIdx.x * blockDim.x + threadIdx.x; i < n;
         i += gridDim.x * blockDim.x)
        g_count[i] = 0;
    if (blockIdx.x == 0 && threadIdx.x < 2) g_acc[threadIdx.x] = 0.0;
}

// ---------------------------------------------------------------------------
__global__ void count_kernel(const float* __restrict__ pred,
                             const float* __restrict__ tgt) {
    int tid = blockIdx.x * blockDim.x + threadIdx.x;
    if (tid >= NGRIDS * NN) return;
    int g = tid >> 14, i = tid & (NN - 1);
    int batch = g >> 1, side = g & 1;
    const float* p = (side ? tgt : pred) + (size_t)(batch * NN + i) * 3;
    int c = (cell_of(p[2]) * G + cell_of(p[1])) * G + cell_of(p[0]);
    atomicAdd(&g_count[g * NC + c], 1);
}

// ---------------------------------------------------------------------------
// One block per grid: 1024 threads, 256 cells each. Produces exclusive prefix
// in g_start and re-zeroes g_count (so it can serve as the scatter cursor).
__global__ void scan_kernel() {
    __shared__ int sh[1024];
    int g = blockIdx.x;
    int t = threadIdx.x;
    int* cnt = g_count + g * NC;
    int* st  = g_start + g * (NC + 1);
    int base = t * 256;

    int sum = 0;
#pragma unroll 8
    for (int i = 0; i < 256; i++) sum += cnt[base + i];
    sh[t] = sum;
    __syncthreads();
    // Hillis-Steele inclusive scan over 1024 partials
    for (int off = 1; off < 1024; off <<= 1) {
        int v = (t >= off) ? sh[t - off] : 0;
        __syncthreads();
        sh[t] += v;
        __syncthreads();
    }
    int run = sh[t] - sum;  // exclusive prefix for this thread's chunk
    for (int i = 0; i < 256; i++) {
        int c = base + i;
        int v = cnt[c];
        st[c] = run;
        run += v;
        cnt[c] = 0;
    }
    if (t == 1023) st[NC] = run;  // == NN
}

// ---------------------------------------------------------------------------
__global__ void scatter_kernel(const float* __restrict__ pred,
                               const float* __restrict__ tgt) {
    int tid = blockIdx.x * blockDim.x + threadIdx.x;
    if (tid >= NGRIDS * NN) return;
    int g = tid >> 14, i = tid & (NN - 1);
    int batch = g >> 1, side = g & 1;
    const float* p = (side ? tgt : pred) + (size_t)(batch * NN + i) * 3;
    float x = p[0], y = p[1], z = p[2];
    int c = (cell_of(z) * G + cell_of(y)) * G + cell_of(x);
    int idx = g_start[g * (NC + 1) + c] + atomicAdd(&g_count[g * NC + c], 1);
    g_pts[g * NN + idx] = make_float4(x, y, z, 0.0f);
}

// ---------------------------------------------------------------------------
// Each thread: one query point (taken from its own side's SORTED array for
// warp-coherent traversal), exact expanding-shell NN search on the opposite
// side's grid. Rows of cells in x are contiguous point ranges -> one
// [start, end) scan per row segment.
__global__ void query_kernel() {
    int tid = blockIdx.x * blockDim.x + threadIdx.x;
    float best = 3.4e38f;

    if (tid < NGRIDS * NN) {
        int qg = tid >> 14, i = tid & (NN - 1);
        int batch = qg >> 1, side = qg & 1;
        int tg = batch * 2 + (1 - side);  // opposite side's grid

        float4 p = g_pts[qg * NN + i];
        const int*    st  = g_start + tg * (NC + 1);
        const float4* pts = g_pts + (size_t)tg * NN;

        int cx = cell_of(p.x), cy = cell_of(p.y), cz = cell_of(p.z);

        for (int r = 0; r < G; r++) {
            int z0 = max(cz - r, 0), z1 = min(cz + r, G - 1);
            int y0 = max(cy - r, 0), y1 = min(cy + r, G - 1);
            int xl = max(cx - r, 0), xh = min(cx + r, G - 1);

            for (int z = z0; z <= z1; z++) {
                bool ze = (z == cz - r) || (z == cz + r);
                int zb = z * (G * G);
                for (int y = y0; y <= y1; y++) {
                    bool edge = ze || (y == cy - r) || (y == cy + r);
                    int cb = zb + y * G;
                    if (edge) {
                        // full x-row: contiguous point range
                        int b0 = st[cb + xl];
                        int e0 = st[cb + xh + 1];
                        for (int k = b0; k < e0; k++) {
                            float4 q = pts[k];
                            float dx = p.x - q.x, dy = p.y - q.y, dz = p.z - q.z;
                            best = fminf(best, dx * dx + dy * dy + dz * dz);
                        }
                    } else {
                        // interior row: only the two x-faces of the shell
                        if (cx - r >= 0) {
                            int c = cb + cx - r;
                            int b0 = st[c], e0 = st[c + 1];
                            for (int k = b0; k < e0; k++) {
                                float4 q = pts[k];
                                float dx = p.x - q.x, dy = p.y - q.y, dz = p.z - q.z;
                                best = fminf(best, dx * dx + dy * dy + dz * dz);
                            }
                        }
                        if (cx + r <= G - 1) {
                            int c = cb + cx + r;
                            int b0 = st[c], e0 = st[c + 1];
                            for (int k = b0; k < e0; k++) {
                                float4 q = pts[k];
                                float dx = p.x - q.x, dy = p.y - q.y, dz = p.z - q.z;
                                best = fminf(best, dx * dx + dy * dy + dz * dz);
                            }
                        }
                    }
                }
            }
            // Exact termination: any unscanned point is >= r*cs away.
            float bd = (float)r * CS_SAFE;
            if (best <= bd * bd) break;
        }
    }

    // Block-wide sum of best (256 threads = 8 warps)
    float v = (tid < NGRIDS * NN) ? best : 0.0f;
#pragma unroll
    for (int o = 16; o > 0; o >>= 1) v += __shfl_down_sync(0xffffffffu, v, o);
    __shared__ float ws[8];
    int lane = threadIdx.x & 31, w = threadIdx.x >> 5;
    if (lane == 0) ws[w] = v;
    __syncthreads();
    if (w == 0) {
        v = (lane < (blockDim.x >> 5)) ? ws[lane] : 0.0f;
#pragma unroll
        for (int o = 4; o > 0; o >>= 1) v += __shfl_down_sync(0xffu, v, o);
        if (lane == 0) atomicAdd(&g_acc[1], (double)v);
    }
}

// ---------------------------------------------------------------------------
__global__ void noise_kernel(const float* __restrict__ a,
                             const float* __restrict__ b, int n) {
    float s = 0.0f;
    for (int i = blockIdx.x * blockDim.x + threadIdx.x; i < n;
         i += gridDim.x * blockDim.x)
        s += fabsf(a[i] - b[i]);
#pragma unroll
    for (int o = 16; o > 0; o >>= 1) s += __shfl_down_sync(0xffffffffu, s, o);
    __shared__ float ws[8];
    int lane = threadIdx.x & 31, w = threadIdx.x >> 5;
    if (lane == 0) ws[w] = s;
    __syncthreads();
    if (w == 0) {
        s = (lane < (blockDim.x >> 5)) ? ws[lane] : 0.0f;
#pragma unroll
        for (int o = 4; o > 0; o >>= 1) s += __shfl_down_sync(0xffu, s, o);
        if (lane == 0) atomicAdd(&g_acc[0], (double)s);
    }
}

// ---------------------------------------------------------------------------
__global__ void finalize_kernel(float* out) {
    // noise mean over B*N*3; chamfer: sum of all 2*B*N min-d2 divided by B*N
    double noise   = g_acc[0] / (double)(BB * NN * 3);
    double chamfer = g_acc[1] / (double)(BB * NN);
    out[0] = (float)(noise + 0.1 * chamfer);
}

// ---------------------------------------------------------------------------
extern "C" void kernel_launch(void* const* d_in, const int* in_sizes, int n_in,
                              void* d_out, int out_size) {
    const float* pn = (const float*)d_in[0];  // predicted_noise
    const float* an = (const float*)d_in[1];  // actual_noise
    const float* pp = (const float*)d_in[2];  // predicted_points_coarse
    const float* tp = (const float*)d_in[3];  // target_points_coarse
    float* out = (float*)d_out;

    zero_kernel<<<2048, 1024>>>();
    count_kernel<<<(NGRIDS * NN + 255) / 256, 256>>>(pp, tp);
    scan_kernel<<<NGRIDS, 1024>>>();
    scatter_kernel<<<(NGRIDS * NN + 255) / 256, 256>>>(pp, tp);
    query_kernel<<<(NGRIDS * NN + 255) / 256, 256>>>();
    noise_kernel<<<512, 256>>>(pn, an, BB * NN * 3);
    finalize_kernel<<<1, 1>>>(out);
}